// round 7
// baseline (speedup 1.0000x reference)
#include <cuda_runtime.h>
#include <cuda_fp16.h>
#include <math.h>
#include <stdint.h>

typedef uint32_t u32;

#define MROWS 65536
#define NBLH  4096
#define OUT_ELEMS ((size_t)MROWS * 256)

// Scratch
__device__ u32 g_attnout[(size_t)MROWS * 128];  // [m][d/2] fp16 pairs
__device__ u32 g_wh[4 * 32768];                 // Wq,Wk,Wv,Wfc as fp16 pairs [n][k/2]

// ---------------------------------------------------------------------------
// helpers
// ---------------------------------------------------------------------------
__device__ __forceinline__ u32 f2h2(float lo, float hi) {
    __half2 h = __floats2half2_rn(lo, hi);
    return *reinterpret_cast<u32*>(&h);
}
__device__ __forceinline__ void mma_f16(float* d, const u32* a, u32 b0, u32 b1) {
    asm volatile(
        "mma.sync.aligned.m16n8k16.row.col.f32.f16.f16.f32 "
        "{%0,%1,%2,%3}, {%4,%5,%6,%7}, {%8,%9}, {%0,%1,%2,%3};"
        : "+f"(d[0]), "+f"(d[1]), "+f"(d[2]), "+f"(d[3])
        : "r"(a[0]), "r"(a[1]), "r"(a[2]), "r"(a[3]), "r"(b0), "r"(b1));
}
__device__ __forceinline__ void ldmx4(u32* r, u32 addr) {
    asm volatile("ldmatrix.sync.aligned.m8n8.x4.shared.b16 {%0,%1,%2,%3}, [%4];"
        : "=r"(r[0]), "=r"(r[1]), "=r"(r[2]), "=r"(r[3]) : "r"(addr));
}
__device__ __forceinline__ void ldmx4t(u32* r, u32 addr) {
    asm volatile("ldmatrix.sync.aligned.m8n8.x4.trans.shared.b16 {%0,%1,%2,%3}, [%4];"
        : "=r"(r[0]), "=r"(r[1]), "=r"(r[2]), "=r"(r[3]) : "r"(addr));
}
__device__ __forceinline__ u32 smem_u32(const void* p) {
    u32 a;
    asm("{ .reg .u64 t; cvta.to.shared.u64 t, %1; cvt.u32.u64 %0, t; }" : "=r"(a) : "l"(p));
    return a;
}
__device__ __forceinline__ void cp16(u32 dst, const void* src) {
    asm volatile("cp.async.cg.shared.global [%0], [%1], 16;" :: "r"(dst), "l"(src));
}
#define CP_COMMIT() asm volatile("cp.async.commit_group;")
#define CP_WAIT(n)  asm volatile("cp.async.wait_group %0;" :: "n"(n))

// smem row strides (u32 words)
#define SW  20     // 16 data + 4 pad (k=32 fp16 rows)
#define SWX 12     // 8 data + 4 pad  (k=16 fp16 rows)
#define WS  132    // 128 data + 4 pad (k=256 fp16 rows)

// ---------------------------------------------------------------------------
// Weight pre-conversion to packed fp16
// ---------------------------------------------------------------------------
__global__ void wconv(const float* __restrict__ Wq, const float* __restrict__ Wk,
                      const float* __restrict__ Wv, const float* __restrict__ Wfc)
{
    int i = blockIdx.x * 256 + threadIdx.x;   // 0..32767
    g_wh[i]             = f2h2(Wq[2 * i],  Wq[2 * i + 1]);
    g_wh[32768 + i]     = f2h2(Wk[2 * i],  Wk[2 * i + 1]);
    g_wh[2 * 32768 + i] = f2h2(Wv[2 * i],  Wv[2 * i + 1]);
    g_wh[3 * 32768 + i] = f2h2(Wfc[2 * i], Wfc[2 * i + 1]);
}

// ---------------------------------------------------------------------------
// Fused kernel: per (b,l,h) CTA. Phase 1: Q/K/V slice GEMMs (128x32, K=256,
// BK=16, 3-stage sts pipeline). Phase 2: attention (round-5 body) on the
// in-smem tiles. Writes attn probs (fp32) + O (fp16 pairs to g_attnout).
// ---------------------------------------------------------------------------
#define XSTG   (128 * SWX)          // 1536 words: one matrix, one stage
#define XSTG3  (3 * XSTG)           // 4608 words: all 3 matrices, one stage
#define PA_W_OFF (3 * XSTG3)        // W tiles after 3 X stages: 13824
#define PA_SMEM_W (PA_W_OFF + 3 * 32 * WS)   // 13824 + 12672 = 26496 words
#define PA_SMEM_BYTES (PA_SMEM_W * 4)        // 105984 B

__global__ __launch_bounds__(256, 2) void proj_attn(
    const float* __restrict__ q, const float* __restrict__ k, const float* __restrict__ v,
    const float* __restrict__ bq, const float* __restrict__ bk, const float* __restrict__ bv,
    float* __restrict__ attn_out)
{
    extern __shared__ u32 dyn[];
    const u32 sb = smem_u32(dyn);

    const int blk  = blockIdx.x;          // blq*8 + h
    const int blq  = blk >> 3;
    const int h    = blk & 7;
    const int tid  = threadIdx.x;
    const int wid  = tid >> 5;
    const int lane = tid & 31;
    const int g    = lane >> 2;
    const int t    = lane & 3;
    const int lr   = lane & 15;
    const int lc   = (lane >> 4) * 4;

    const float* Xq = q + (size_t)blq * 128 * 256;
    const float* Xk = k + (size_t)blq * 128 * 256;
    const float* Xv = v + (size_t)blq * 128 * 256;

    // ---- W slices (rows h*32 .. h*32+31 of Wq/Wk/Wv) via cp.async ----
    #pragma unroll
    for (int z = 0; z < 3; z++) {
        const u32* Wsrc = g_wh + (size_t)z * 32768 + (size_t)(h * 32) * 128;
        #pragma unroll
        for (int j = 0; j < 4; j++) {
            int idx = tid + j * 256;       // 0..1023
            int r = idx >> 5, c4 = idx & 31;
            cp16(sb + (u32)(PA_W_OFF + z * 32 * WS + r * WS + c4 * 4) * 4,
                 &Wsrc[r * 128 + c4 * 4]);
        }
    }
    CP_COMMIT();

    // ---- X staging: ldg fp32 -> cvt -> sts fp16, chunks of k=16 ----
    const int xrow  = tid >> 1;            // 0..127
    const int xhalf = tid & 1;             // 8 floats each

    float4 fq[2], fk[2], fv[2];
#define LDG_X(kcc)                                                             \
    do {                                                                       \
        size_t _o = (size_t)xrow * 256 + (kcc) * 16 + xhalf * 8;               \
        fq[0] = *(const float4*)&Xq[_o]; fq[1] = *(const float4*)&Xq[_o + 4];  \
        fk[0] = *(const float4*)&Xk[_o]; fk[1] = *(const float4*)&Xk[_o + 4];  \
        fv[0] = *(const float4*)&Xv[_o]; fv[1] = *(const float4*)&Xv[_o + 4];  \
    } while (0)
#define STS_X(stoff)                                                           \
    do {                                                                       \
        u32* _d = &dyn[(stoff) + xrow * SWX + xhalf * 4];                      \
        _d[0] = f2h2(fq[0].x, fq[0].y); _d[1] = f2h2(fq[0].z, fq[0].w);        \
        _d[2] = f2h2(fq[1].x, fq[1].y); _d[3] = f2h2(fq[1].z, fq[1].w);        \
        _d += XSTG;                                                            \
        _d[0] = f2h2(fk[0].x, fk[0].y); _d[1] = f2h2(fk[0].z, fk[0].w);        \
        _d[2] = f2h2(fk[1].x, fk[1].y); _d[3] = f2h2(fk[1].z, fk[1].w);        \
        _d += XSTG;                                                            \
        _d[0] = f2h2(fv[0].x, fv[0].y); _d[1] = f2h2(fv[0].z, fv[0].w);        \
        _d[2] = f2h2(fv[1].x, fv[1].y); _d[3] = f2h2(fv[1].z, fv[1].w);        \
    } while (0)

    LDG_X(0); STS_X(0);
    LDG_X(1); STS_X(XSTG3);
    LDG_X(2);                      // chunk 2 held in regs
    CP_WAIT(0);                    // W tiles resident
    __syncthreads();

    // ---- GEMM mainloop: 16 chunks of k=16 ----
    float acc[3][4][4];
    #pragma unroll
    for (int z = 0; z < 3; z++)
        #pragma unroll
        for (int nt = 0; nt < 4; nt++)
            #pragma unroll
            for (int c = 0; c < 4; c++) acc[z][nt][c] = 0.0f;

    int rd = 0, wr = 2 * XSTG3;    // read stage kc%3, write stage (kc+2)%3

    #pragma unroll 1
    for (int kc = 0; kc < 16; kc++) {
        if (kc) __syncthreads();
        if (kc < 14) STS_X(wr);
        if (kc < 13) LDG_X(kc + 3);

        const u32 a_base = sb + (u32)rd * 4;
        const u32 w_col  = (u32)(kc * 8 + lc);
        #pragma unroll
        for (int z = 0; z < 3; z++) {
            u32 ra[4];
            ldmx4(ra, a_base + (u32)(z * XSTG + (wid * 16 + lr) * SWX + lc) * 4);
            const u32 wb = sb + (u32)(PA_W_OFF + z * 32 * WS) * 4;
            u32 rb0[4], rb1[4];
            ldmx4(rb0, wb + (u32)(lr * WS) * 4 + w_col * 4);
            ldmx4(rb1, wb + (u32)((16 + lr) * WS) * 4 + w_col * 4);
            mma_f16(acc[z][0], ra, rb0[0], rb0[2]);
            mma_f16(acc[z][1], ra, rb0[1], rb0[3]);
            mma_f16(acc[z][2], ra, rb1[0], rb1[2]);
            mma_f16(acc[z][3], ra, rb1[1], rb1[3]);
        }
        rd = (rd == 2 * XSTG3) ? 0 : rd + XSTG3;
        wr = (wr == 2 * XSTG3) ? 0 : wr + XSTG3;
    }
    __syncthreads();   // all stage reads done; reuse X area for Q/K/V tiles

    // ---- epilogue phase 1: bias (+scale for Q), pack fp16, store to smem ----
    // Qs = dyn[0..2560), Ks = dyn[2560..5120), Vs = dyn[5120..7680), stride SW
    {
        const int row = wid * 16 + g;
        #pragma unroll
        for (int z = 0; z < 3; z++) {
            const float* bz = (z == 0) ? bq : (z == 1) ? bk : bv;
            const float sc  = (z == 0) ? 0.17677669529663687f : 1.0f;
            const int dst   = z * 2560;
            #pragma unroll
            for (int nt = 0; nt < 4; nt++) {
                int n = nt * 8 + 2 * t;
                float b0 = bz[h * 32 + n], b1 = bz[h * 32 + n + 1];
                #pragma unroll
                for (int rs = 0; rs < 2; rs++) {
                    dyn[dst + (row + 8 * rs) * SW + nt * 4 + t] =
                        f2h2((acc[z][nt][2 * rs]     + b0) * sc,
                             (acc[z][nt][2 * rs + 1] + b1) * sc);
                }
            }
        }
    }
    __syncthreads();

    // ---- phase 2: attention (round-5 body) ----
    const u32 qs_b = sb;
    const u32 ks_b = sb + 2560 * 4;
    const u32 vs_b = sb + 5120 * 4;

    float sacc[16][4];
    #pragma unroll
    for (int nt = 0; nt < 16; nt++)
        #pragma unroll
        for (int c = 0; c < 4; c++) sacc[nt][c] = 0.0f;

    const int rbase16 = wid * 16;
    const int rbase   = rbase16 + g;
    #pragma unroll
    for (int c = 0; c < 2; c++) {
        u32 ra[4];
        ldmx4(ra, qs_b + (u32)((rbase16 + lr) * SW + c * 8 + lc) * 4);
        #pragma unroll
        for (int qq = 0; qq < 8; qq++) {
            u32 rb[4];
            ldmx4(rb, ks_b + (u32)((qq * 16 + lr) * SW + c * 8 + lc) * 4);
            mma_f16(sacc[2 * qq],     ra, rb[0], rb[2]);
            mma_f16(sacc[2 * qq + 1], ra, rb[1], rb[3]);
        }
    }

    float inv[2];
    #pragma unroll
    for (int rs = 0; rs < 2; rs++) {
        float mx = -1e30f;
        #pragma unroll
        for (int nt = 0; nt < 16; nt++) {
            mx = fmaxf(mx, sacc[nt][2 * rs]);
            mx = fmaxf(mx, sacc[nt][2 * rs + 1]);
        }
        mx = fmaxf(mx, __shfl_xor_sync(0xffffffffu, mx, 1));
        mx = fmaxf(mx, __shfl_xor_sync(0xffffffffu, mx, 2));
        float s = 0.0f;
        #pragma unroll
        for (int nt = 0; nt < 16; nt++) {
            float e0 = __expf(sacc[nt][2 * rs] - mx);
            float e1 = __expf(sacc[nt][2 * rs + 1] - mx);
            sacc[nt][2 * rs] = e0; sacc[nt][2 * rs + 1] = e1;
            s += e0 + e1;
        }
        s += __shfl_xor_sync(0xffffffffu, s, 1);
        s += __shfl_xor_sync(0xffffffffu, s, 2);
        inv[rs] = 1.0f / s;
    }
    #pragma unroll
    for (int nt = 0; nt < 16; nt++) {
        sacc[nt][0] *= inv[0]; sacc[nt][1] *= inv[0];
        sacc[nt][2] *= inv[1]; sacc[nt][3] *= inv[1];
    }

    const size_t abase = (size_t)blk * 16384;
    #pragma unroll
    for (int nt = 0; nt < 16; nt++) {
        int col = nt * 8 + 2 * t;
        float2 p0; p0.x = sacc[nt][0]; p0.y = sacc[nt][1];
        float2 p1; p1.x = sacc[nt][2]; p1.y = sacc[nt][3];
        *(float2*)&attn_out[abase + (size_t)rbase * 128 + col]       = p0;
        *(float2*)&attn_out[abase + (size_t)(rbase + 8) * 128 + col] = p1;
    }

    float oacc[4][4];
    #pragma unroll
    for (int nt = 0; nt < 4; nt++)
        #pragma unroll
        for (int c = 0; c < 4; c++) oacc[nt][c] = 0.0f;

    const int vrow_off = ((lane >> 3) & 1) * 8 + (lane & 7);
    const int vcol_off = (lane >> 4) * 4;
    #pragma unroll
    for (int ks = 0; ks < 8; ks++) {
        u32 af[4];
        af[0] = f2h2(sacc[2 * ks][0],     sacc[2 * ks][1]);
        af[1] = f2h2(sacc[2 * ks][2],     sacc[2 * ks][3]);
        af[2] = f2h2(sacc[2 * ks + 1][0], sacc[2 * ks + 1][1]);
        af[3] = f2h2(sacc[2 * ks + 1][2], sacc[2 * ks + 1][3]);
        #pragma unroll
        for (int np = 0; np < 2; np++) {
            u32 rb[4];
            ldmx4t(rb, vs_b + (u32)((16 * ks + vrow_off) * SW + np * 8 + vcol_off) * 4);
            mma_f16(oacc[2 * np],     af, rb[0], rb[1]);
            mma_f16(oacc[2 * np + 1], af, rb[2], rb[3]);
        }
    }

    #pragma unroll
    for (int nt = 0; nt < 4; nt++) {
        #pragma unroll
        for (int rs = 0; rs < 2; rs++) {
            int m = blq * 128 + rbase + 8 * rs;
            g_attnout[(size_t)m * 128 + h * 16 + nt * 4 + t] =
                f2h2(oacc[nt][2 * rs], oacc[nt][2 * rs + 1]);
        }
    }
}

// ---------------------------------------------------------------------------
// Kernel C: FC + residual + LayerNorm (round-5 2-stage version, measured 67us)
// ---------------------------------------------------------------------------
#define FC_AS_W (2 * 128 * SW)
#define FC_BS_W (2 * 256 * SW)
#define FC_SMEM_BYTES ((FC_AS_W + FC_BS_W + 1024) * 4)

__global__ __launch_bounds__(512, 1) void fc_ln_kernel(
    const float* __restrict__ bfc, const float* __restrict__ resid,
    const float* __restrict__ ln_w, const float* __restrict__ ln_b,
    float* __restrict__ out)
{
    extern __shared__ u32 dyn[];
    u32*  As  = dyn;
    u32*  Bs  = dyn + FC_AS_W;
    float* red = (float*)(dyn + FC_AS_W + FC_BS_W);   // [128][8]

    const u32* Wt = g_wh + 3 * 32768;
    const int tid  = threadIdx.x;
    const int wid  = tid >> 5;
    const int lane = tid & 31;
    const int g    = lane >> 2;
    const int t    = lane & 3;
    const int lr   = lane & 15;
    const int lc   = (lane >> 4) * 4;
    const int wm   = wid >> 2;   // 0..3
    const int wn   = wid & 3;    // 0..3
    const size_t m0 = (size_t)blockIdx.x * 128;

    const u32 as_b = smem_u32(As);
    const u32 bs_b = smem_u32(Bs);

    #pragma unroll
    for (int st = 0; st < 2; st++) {
        {
            int r = tid >> 2, c4 = tid & 3;
            cp16(as_b + (u32)(st * 128 * SW + r * SW + c4 * 4) * 4,
                 &g_attnout[(m0 + r) * 128 + st * 16 + c4 * 4]);
        }
        #pragma unroll
        for (int j = 0; j < 2; j++) {
            int idx = tid + j * 512; int r = idx >> 2, c4 = idx & 3;
            cp16(bs_b + (u32)(st * 256 * SW + r * SW + c4 * 4) * 4,
                 &Wt[(size_t)r * 128 + st * 16 + c4 * 4]);
        }
        CP_COMMIT();
    }

    float acc[2][8][4];
    #pragma unroll
    for (int a = 0; a < 2; a++)
        #pragma unroll
        for (int b = 0; b < 8; b++)
            #pragma unroll
            for (int c = 0; c < 4; c++) acc[a][b][c] = 0.0f;

    #pragma unroll 1
    for (int i = 0; i < 8; i++) {
        const int s = i & 1;
        if (i < 7) { CP_WAIT(1); } else { CP_WAIT(0); }
        __syncthreads();

        const u32 a0 = as_b + (u32)s * 128 * SW * 4;
        const u32 b0 = bs_b + (u32)s * 256 * SW * 4;
        #pragma unroll
        for (int c = 0; c < 2; c++) {
            u32 ra[2][4];
            #pragma unroll
            for (int mt = 0; mt < 2; mt++)
                ldmx4(ra[mt], a0 + (u32)((wm * 32 + mt * 16 + lr) * SW + c * 8 + lc) * 4);
            #pragma unroll
            for (int qq = 0; qq < 4; qq++) {
                u32 rb[4];
                ldmx4(rb, b0 + (u32)((wn * 64 + qq * 16 + lr) * SW + c * 8 + lc) * 4);
                #pragma unroll
                for (int mt = 0; mt < 2; mt++) {
                    mma_f16(acc[mt][2 * qq],     ra[mt], rb[0], rb[2]);
                    mma_f16(acc[mt][2 * qq + 1], ra[mt], rb[1], rb[3]);
                }
            }
        }
        __syncthreads();
        if (i < 6) {
            {
                int r = tid >> 2, c4 = tid & 3;
                cp16(as_b + (u32)(s * 128 * SW + r * SW + c4 * 4) * 4,
                     &g_attnout[(m0 + r) * 128 + (i + 2) * 16 + c4 * 4]);
            }
            #pragma unroll
            for (int j = 0; j < 2; j++) {
                int idx = tid + j * 512; int r = idx >> 2, c4 = idx & 3;
                cp16(bs_b + (u32)(s * 256 * SW + r * SW + c4 * 4) * 4,
                     &Wt[(size_t)r * 128 + (i + 2) * 16 + c4 * 4]);
            }
            CP_COMMIT();
        }
    }

    #pragma unroll
    for (int mt = 0; mt < 2; mt++) {
        #pragma unroll
        for (int rs = 0; rs < 2; rs++) {
            int rloc = wm * 32 + mt * 16 + g + 8 * rs;
            float s = 0.0f, sq = 0.0f;
            #pragma unroll
            for (int nt = 0; nt < 8; nt++) {
                int col = wn * 64 + nt * 8 + 2 * t;
                float2 rr = *(const float2*)&resid[(m0 + rloc) * 256 + col];
                float v0 = acc[mt][nt][2 * rs]     + bfc[col]     + rr.x;
                float v1 = acc[mt][nt][2 * rs + 1] + bfc[col + 1] + rr.y;
                acc[mt][nt][2 * rs]     = v0;
                acc[mt][nt][2 * rs + 1] = v1;
                s  += v0 + v1;
                sq += v0 * v0 + v1 * v1;
            }
            s  += __shfl_xor_sync(0xffffffffu, s, 1);
            s  += __shfl_xor_sync(0xffffffffu, s, 2);
            sq += __shfl_xor_sync(0xffffffffu, sq, 1);
            sq += __shfl_xor_sync(0xffffffffu, sq, 2);
            if (t == 0) {
                red[rloc * 8 + wn]     = s;
                red[rloc * 8 + 4 + wn] = sq;
            }
        }
    }
    __syncthreads();

    #pragma unroll
    for (int mt = 0; mt < 2; mt++) {
        #pragma unroll
        for (int rs = 0; rs < 2; rs++) {
            int rloc = wm * 32 + mt * 16 + g + 8 * rs;
            float s  = red[rloc * 8 + 0] + red[rloc * 8 + 1] + red[rloc * 8 + 2] + red[rloc * 8 + 3];
            float sq = red[rloc * 8 + 4] + red[rloc * 8 + 5] + red[rloc * 8 + 6] + red[rloc * 8 + 7];
            float mu   = s * (1.0f / 256.0f);
            float var  = sq * (1.0f / 256.0f) - mu * mu;
            float rstd = rsqrtf(var + 1e-6f);
            #pragma unroll
            for (int nt = 0; nt < 8; nt++) {
                int col = wn * 64 + nt * 8 + 2 * t;
                float2 lw = *(const float2*)&ln_w[col];
                float2 lb = *(const float2*)&ln_b[col];
                float2 o;
                o.x = (acc[mt][nt][2 * rs]     - mu) * rstd * lw.x + lb.x;
                o.y = (acc[mt][nt][2 * rs + 1] - mu) * rstd * lw.y + lb.y;
                *(float2*)&out[(m0 + rloc) * 256 + col] = o;
            }
        }
    }
}

// ---------------------------------------------------------------------------
extern "C" void kernel_launch(void* const* d_in, const int* in_sizes, int n_in,
                              void* d_out, int out_size)
{
    const float* q    = (const float*)d_in[0];
    const float* k    = (const float*)d_in[1];
    const float* v    = (const float*)d_in[2];
    const float* Wq   = (const float*)d_in[3];
    const float* bq   = (const float*)d_in[4];
    const float* Wk   = (const float*)d_in[5];
    const float* bk   = (const float*)d_in[6];
    const float* Wv   = (const float*)d_in[7];
    const float* bv   = (const float*)d_in[8];
    const float* Wfc  = (const float*)d_in[9];
    const float* bfc  = (const float*)d_in[10];
    const float* ln_w = (const float*)d_in[11];
    const float* ln_b = (const float*)d_in[12];

    float* out  = (float*)d_out;
    float* attn = out + OUT_ELEMS;

    static bool attr_set = false;
    if (!attr_set) {
        cudaFuncSetAttribute(proj_attn,    cudaFuncAttributeMaxDynamicSharedMemorySize, PA_SMEM_BYTES);
        cudaFuncSetAttribute(fc_ln_kernel, cudaFuncAttributeMaxDynamicSharedMemorySize, FC_SMEM_BYTES);
        attr_set = true;
    }

    wconv<<<128, 256>>>(Wq, Wk, Wv, Wfc);
    proj_attn<<<NBLH, 256, PA_SMEM_BYTES>>>(q, k, v, bq, bk, bv, attn);
    fc_ln_kernel<<<512, 512, FC_SMEM_BYTES>>>(bfc, q, ln_w, ln_b, out);
}

// round 8
// speedup vs baseline: 1.7156x; 1.7156x over previous
#include <cuda_runtime.h>
#include <cuda_fp16.h>
#include <math.h>
#include <stdint.h>

typedef uint32_t u32;

#define MROWS 65536
#define NBLH  4096
#define OUT_ELEMS ((size_t)MROWS * 256)

// Scratch: fp16 pairs packed in u32 words (pairs along the k/d dimension)
__device__ u32 g_qh[(size_t)NBLH * 128 * 16];   // [blq][h][w][dk/2]
__device__ u32 g_kh[(size_t)NBLH * 128 * 16];
__device__ u32 g_vh[(size_t)NBLH * 128 * 16];
__device__ u32 g_attnout[(size_t)MROWS * 128];  // [m][d/2]
__device__ u32 g_wh[4 * 32768];                 // Wq,Wk,Wv,Wfc as fp16 pairs [n][k/2]

// ---------------------------------------------------------------------------
// helpers
// ---------------------------------------------------------------------------
__device__ __forceinline__ u32 f2h2(float lo, float hi) {
    __half2 h = __floats2half2_rn(lo, hi);
    return *reinterpret_cast<u32*>(&h);
}
__device__ __forceinline__ void mma_f16(float* d, const u32* a, u32 b0, u32 b1) {
    asm volatile(
        "mma.sync.aligned.m16n8k16.row.col.f32.f16.f16.f32 "
        "{%0,%1,%2,%3}, {%4,%5,%6,%7}, {%8,%9}, {%0,%1,%2,%3};"
        : "+f"(d[0]), "+f"(d[1]), "+f"(d[2]), "+f"(d[3])
        : "r"(a[0]), "r"(a[1]), "r"(a[2]), "r"(a[3]), "r"(b0), "r"(b1));
}
__device__ __forceinline__ void ldmx4(u32* r, u32 addr) {
    asm volatile("ldmatrix.sync.aligned.m8n8.x4.shared.b16 {%0,%1,%2,%3}, [%4];"
        : "=r"(r[0]), "=r"(r[1]), "=r"(r[2]), "=r"(r[3]) : "r"(addr));
}
__device__ __forceinline__ void ldmx4t(u32* r, u32 addr) {
    asm volatile("ldmatrix.sync.aligned.m8n8.x4.trans.shared.b16 {%0,%1,%2,%3}, [%4];"
        : "=r"(r[0]), "=r"(r[1]), "=r"(r[2]), "=r"(r[3]) : "r"(addr));
}
__device__ __forceinline__ u32 smem_u32(const void* p) {
    u32 a;
    asm("{ .reg .u64 t; cvta.to.shared.u64 t, %1; cvt.u32.u64 %0, t; }" : "=r"(a) : "l"(p));
    return a;
}
__device__ __forceinline__ void cp16(u32 dst, const void* src) {
    asm volatile("cp.async.cg.shared.global [%0], [%1], 16;" :: "r"(dst), "l"(src));
}
__device__ __forceinline__ void st_cs_f4(float* p, float4 v) {
    asm volatile("st.global.cs.v4.f32 [%0], {%1,%2,%3,%4};"
        :: "l"(p), "f"(v.x), "f"(v.y), "f"(v.z), "f"(v.w) : "memory");
}
#define CP_COMMIT() asm volatile("cp.async.commit_group;")
#define CP_WAIT(n)  asm volatile("cp.async.wait_group %0;" :: "n"(n))

// row stride in u32 words for all [row][k] smem tiles (16 data + 4 pad)
#define SW 20

// ---------------------------------------------------------------------------
// Weight pre-conversion to packed fp16
// ---------------------------------------------------------------------------
__global__ void wconv(const float* __restrict__ Wq, const float* __restrict__ Wk,
                      const float* __restrict__ Wv, const float* __restrict__ Wfc)
{
    int i = blockIdx.x * 256 + threadIdx.x;   // 0..32767
    g_wh[i]             = f2h2(Wq[2 * i],  Wq[2 * i + 1]);
    g_wh[32768 + i]     = f2h2(Wk[2 * i],  Wk[2 * i + 1]);
    g_wh[2 * 32768 + i] = f2h2(Wv[2 * i],  Wv[2 * i + 1]);
    g_wh[3 * 32768 + i] = f2h2(Wfc[2 * i], Wfc[2 * i + 1]);
}

// ---------------------------------------------------------------------------
// Kernel A: QKV projection (fp16 mma), round-5 2-stage pipeline.
// grid (2, 512, 3): x = n-tile fastest -> the 2 CTAs of one m-block are
// co-resident and share the X block in L2 (X DRAM reads halved).
// ---------------------------------------------------------------------------
__global__ __launch_bounds__(256, 2) void gemm_proj(
    const float* __restrict__ q, const float* __restrict__ k, const float* __restrict__ v,
    const float* __restrict__ bq, const float* __restrict__ bk, const float* __restrict__ bv)
{
    __shared__ u32 As[2 * 128 * SW];
    __shared__ u32 Bs[2 * 128 * SW];

    const int z = blockIdx.z;
    const float* X    = (z == 0) ? q : (z == 1) ? k : v;
    const u32*   Wt   = g_wh + (size_t)z * 32768;
    const float* bias = (z == 0) ? bq : (z == 1) ? bk : bv;
    u32*         outp = (z == 0) ? g_qh : (z == 1) ? g_kh : g_vh;
    const float scale = (z == 0) ? 0.17677669529663687f : 1.0f;

    const int tid  = threadIdx.x;
    const int wid  = tid >> 5;
    const int lane = tid & 31;
    const int g    = lane >> 2;
    const int t    = lane & 3;
    const int lr   = lane & 15;
    const int lc   = (lane >> 4) * 4;
    const int wm   = wid >> 2;    // 0..1
    const int wn   = wid & 3;     // 0..3
    const int m0   = blockIdx.y * 128;
    const int n0   = blockIdx.x * 128;

    const u32 as_b = smem_u32(As);
    const u32 bs_b = smem_u32(Bs);

    const int arow  = tid >> 1;      // A ldg: row
    const int ahalf = tid & 1;       // word half

    float4 fa[4];
    // prologue
    #pragma unroll
    for (int j = 0; j < 4; j++)
        fa[j] = *(const float4*)&X[(size_t)(m0 + arow) * 256 + ahalf * 16 + j * 4];
    #pragma unroll
    for (int j = 0; j < 2; j++) {
        int idx = tid + j * 256; int r = idx >> 2, c4 = idx & 3;
        cp16(bs_b + (u32)(r * SW + c4 * 4) * 4, &Wt[(size_t)(n0 + r) * 128 + c4 * 4]);
    }
    CP_COMMIT();
    {
        u32* dst = &As[arow * SW + ahalf * 8];
        #pragma unroll
        for (int j = 0; j < 4; j++) {
            dst[2 * j]     = f2h2(fa[j].x, fa[j].y);
            dst[2 * j + 1] = f2h2(fa[j].z, fa[j].w);
        }
    }
    #pragma unroll
    for (int j = 0; j < 4; j++)
        fa[j] = *(const float4*)&X[(size_t)(m0 + arow) * 256 + 32 + ahalf * 16 + j * 4];
    #pragma unroll
    for (int j = 0; j < 2; j++) {
        int idx = tid + j * 256; int r = idx >> 2, c4 = idx & 3;
        cp16(bs_b + (u32)(128 * SW + r * SW + c4 * 4) * 4, &Wt[(size_t)(n0 + r) * 128 + 16 + c4 * 4]);
    }
    CP_COMMIT();

    float acc[4][4][4];
    #pragma unroll
    for (int a = 0; a < 4; a++)
        #pragma unroll
        for (int b = 0; b < 4; b++)
            #pragma unroll
            for (int c = 0; c < 4; c++) acc[a][b][c] = 0.0f;

    for (int i = 0; i < 8; i++) {
        const int s = i & 1;
        if (i < 7) { CP_WAIT(1); } else { CP_WAIT(0); }
        __syncthreads();

        const u32 a0 = as_b + (u32)s * 128 * SW * 4;
        const u32 b0 = bs_b + (u32)s * 128 * SW * 4;
        #pragma unroll
        for (int c = 0; c < 2; c++) {
            u32 ra[4][4];
            #pragma unroll
            for (int mt = 0; mt < 4; mt++)
                ldmx4(ra[mt], a0 + (u32)((wm * 64 + mt * 16 + lr) * SW + c * 8 + lc) * 4);
            #pragma unroll
            for (int qq = 0; qq < 2; qq++) {
                u32 rb[4];
                ldmx4(rb, b0 + (u32)((wn * 32 + qq * 16 + lr) * SW + c * 8 + lc) * 4);
                #pragma unroll
                for (int mt = 0; mt < 4; mt++) {
                    mma_f16(acc[mt][2 * qq],     ra[mt], rb[0], rb[2]);
                    mma_f16(acc[mt][2 * qq + 1], ra[mt], rb[1], rb[3]);
                }
            }
        }

        if (i < 7) {
            u32* dst = &As[(s ^ 1) * 128 * SW + arow * SW + ahalf * 8];
            #pragma unroll
            for (int j = 0; j < 4; j++) {
                dst[2 * j]     = f2h2(fa[j].x, fa[j].y);
                dst[2 * j + 1] = f2h2(fa[j].z, fa[j].w);
            }
        }
        __syncthreads();
        if (i < 6) {
            #pragma unroll
            for (int j = 0; j < 4; j++)
                fa[j] = *(const float4*)&X[(size_t)(m0 + arow) * 256 + (i + 2) * 32 + ahalf * 16 + j * 4];
            #pragma unroll
            for (int j = 0; j < 2; j++) {
                int idx = tid + j * 256; int r = idx >> 2, c4 = idx & 3;
                cp16(bs_b + (u32)(s * 128 * SW + r * SW + c4 * 4) * 4,
                     &Wt[(size_t)(n0 + r) * 128 + (i + 2) * 16 + c4 * 4]);
            }
            CP_COMMIT();
        }
    }

    // epilogue: bias, scale, pack fp16 pairs, scatter to [blq][h][w][dk/2]
    #pragma unroll
    for (int mt = 0; mt < 4; mt++) {
        #pragma unroll
        for (int nt = 0; nt < 4; nt++) {
            int n  = n0 + wn * 32 + nt * 8 + 2 * t;
            int h  = n >> 5;
            int dw = (n & 31) >> 1;
            float b0v = bias[n], b1v = bias[n + 1];
            #pragma unroll
            for (int rs = 0; rs < 2; rs++) {
                int m   = m0 + wm * 64 + mt * 16 + g + 8 * rs;
                int blq = m >> 7;
                int ww  = m & 127;
                outp[(((size_t)blq * 8 + h) * 128 + ww) * 16 + dw] =
                    f2h2((acc[mt][nt][2 * rs]     + b0v) * scale,
                         (acc[mt][nt][2 * rs + 1] + b1v) * scale);
            }
        }
    }
}

// ---------------------------------------------------------------------------
// Kernel B: attention per (b,l,h). Round-5 math; attn-prob writes staged
// through smem (Ps[128][132]) and copied out coalesced with st.global.cs.v4.
// Dynamic smem: Qs/Ks/Vs (30KB) + Ps (67.6KB) = 96KB -> 2 CTAs/SM.
// ---------------------------------------------------------------------------
#define AT_QS 0
#define AT_KS (128 * SW)
#define AT_VS (2 * 128 * SW)
#define AT_PS (3 * 128 * SW)            // float area, 128*132 words
#define AT_SMEM_W (AT_PS + 128 * 132)
#define AT_SMEM_BYTES (AT_SMEM_W * 4)   // 98304

__global__ __launch_bounds__(256, 2) void attn_kernel(float* __restrict__ attn_out)
{
    extern __shared__ u32 dyn[];
    const u32 qs_b = smem_u32(dyn) + AT_QS * 4;
    const u32 ks_b = smem_u32(dyn) + AT_KS * 4;
    const u32 vs_b = smem_u32(dyn) + AT_VS * 4;
    float* Ps = (float*)(dyn + AT_PS);

    const int blk  = blockIdx.x;
    const int tid  = threadIdx.x;
    const int wid  = tid >> 5;
    const int lane = tid & 31;
    const int g    = lane >> 2;
    const int t    = lane & 3;
    const int lr   = lane & 15;
    const int lc   = (lane >> 4) * 4;

    const uint4* Qg = (const uint4*)(g_qh + (size_t)blk * 2048);
    const uint4* Kg = (const uint4*)(g_kh + (size_t)blk * 2048);
    const uint4* Vg = (const uint4*)(g_vh + (size_t)blk * 2048);

    #pragma unroll
    for (int j = 0; j < 2; j++) {
        int idx = tid + j * 256;
        int row = idx >> 2, q4 = idx & 3;
        *(uint4*)&dyn[AT_QS + row * SW + q4 * 4] = Qg[idx];
        *(uint4*)&dyn[AT_KS + row * SW + q4 * 4] = Kg[idx];
        *(uint4*)&dyn[AT_VS + row * SW + q4 * 4] = Vg[idx];
    }
    __syncthreads();

    // S = Q K^T : 16 rows x 128 cols per warp
    float sacc[16][4];
    #pragma unroll
    for (int nt = 0; nt < 16; nt++)
        #pragma unroll
        for (int c = 0; c < 4; c++) sacc[nt][c] = 0.0f;

    const int rbase16 = wid * 16;
    const int rbase   = rbase16 + g;
    #pragma unroll
    for (int c = 0; c < 2; c++) {
        u32 ra[4];
        ldmx4(ra, qs_b + (u32)((rbase16 + lr) * SW + c * 8 + lc) * 4);
        #pragma unroll
        for (int qq = 0; qq < 8; qq++) {
            u32 rb[4];
            ldmx4(rb, ks_b + (u32)((qq * 16 + lr) * SW + c * 8 + lc) * 4);
            mma_f16(sacc[2 * qq],     ra, rb[0], rb[2]);
            mma_f16(sacc[2 * qq + 1], ra, rb[1], rb[3]);
        }
    }

    // softmax (rows shared within lane quads via xor 1,2)
    float inv[2];
    #pragma unroll
    for (int rs = 0; rs < 2; rs++) {
        float mx = -1e30f;
        #pragma unroll
        for (int nt = 0; nt < 16; nt++) {
            mx = fmaxf(mx, sacc[nt][2 * rs]);
            mx = fmaxf(mx, sacc[nt][2 * rs + 1]);
        }
        mx = fmaxf(mx, __shfl_xor_sync(0xffffffffu, mx, 1));
        mx = fmaxf(mx, __shfl_xor_sync(0xffffffffu, mx, 2));
        float s = 0.0f;
        #pragma unroll
        for (int nt = 0; nt < 16; nt++) {
            float e0 = __expf(sacc[nt][2 * rs] - mx);
            float e1 = __expf(sacc[nt][2 * rs + 1] - mx);
            sacc[nt][2 * rs] = e0; sacc[nt][2 * rs + 1] = e1;
            s += e0 + e1;
        }
        s += __shfl_xor_sync(0xffffffffu, s, 1);
        s += __shfl_xor_sync(0xffffffffu, s, 2);
        inv[rs] = 1.0f / s;
    }
    #pragma unroll
    for (int nt = 0; nt < 16; nt++) {
        sacc[nt][0] *= inv[0]; sacc[nt][1] *= inv[0];
        sacc[nt][2] *= inv[1]; sacc[nt][3] *= inv[1];
    }

    // O = P V first (sacc still live), A-frags packed from sacc
    float oacc[4][4];
    #pragma unroll
    for (int nt = 0; nt < 4; nt++)
        #pragma unroll
        for (int c = 0; c < 4; c++) oacc[nt][c] = 0.0f;

    const int vrow_off = ((lane >> 3) & 1) * 8 + (lane & 7);
    const int vcol_off = (lane >> 4) * 4;
    #pragma unroll
    for (int ks = 0; ks < 8; ks++) {
        u32 af[4];
        af[0] = f2h2(sacc[2 * ks][0],     sacc[2 * ks][1]);
        af[1] = f2h2(sacc[2 * ks][2],     sacc[2 * ks][3]);
        af[2] = f2h2(sacc[2 * ks + 1][0], sacc[2 * ks + 1][1]);
        af[3] = f2h2(sacc[2 * ks + 1][2], sacc[2 * ks + 1][3]);
        #pragma unroll
        for (int np = 0; np < 2; np++) {
            u32 rb[4];
            ldmx4t(rb, vs_b + (u32)((16 * ks + vrow_off) * SW + np * 8 + vcol_off) * 4);
            mma_f16(oacc[2 * np],     af, rb[0], rb[1]);
            mma_f16(oacc[2 * np + 1], af, rb[2], rb[3]);
        }
    }

    // stage probs into Ps[128][132]
    #pragma unroll
    for (int nt = 0; nt < 16; nt++) {
        int col = nt * 8 + 2 * t;
        *(float2*)&Ps[rbase * 132 + col]       = make_float2(sacc[nt][0], sacc[nt][1]);
        *(float2*)&Ps[(rbase + 8) * 132 + col] = make_float2(sacc[nt][2], sacc[nt][3]);
    }
    __syncthreads();

    // coalesced streaming copy: 4096 float4, 16 per thread; each warp covers
    // a full 512B row segment per instruction.
    const size_t abase = (size_t)blk * 16384;
    #pragma unroll
    for (int kk = 0; kk < 16; kk++) {
        int idx = tid + kk * 256;         // 0..4095
        int row = idx >> 5, c4 = idx & 31;
        float4 val = *(const float4*)&Ps[row * 132 + c4 * 4];
        st_cs_f4(&attn_out[abase + (size_t)row * 128 + c4 * 4], val);
    }

    // store O as fp16 pairs to [m][d/2]
    const int blq = blk >> 3;
    const int h   = blk & 7;
    #pragma unroll
    for (int nt = 0; nt < 4; nt++) {
        #pragma unroll
        for (int rs = 0; rs < 2; rs++) {
            int m = blq * 128 + rbase + 8 * rs;
            g_attnout[(size_t)m * 128 + h * 16 + nt * 4 + t] =
                f2h2(oacc[nt][2 * rs], oacc[nt][2 * rs + 1]);
        }
    }
}

// ---------------------------------------------------------------------------
// Kernel C: FC + residual + LayerNorm (round-5 2-stage version, measured 67us)
// ---------------------------------------------------------------------------
#define FC_AS_W (2 * 128 * SW)
#define FC_BS_W (2 * 256 * SW)
#define FC_SMEM_BYTES ((FC_AS_W + FC_BS_W + 1024) * 4)

__global__ __launch_bounds__(512, 1) void fc_ln_kernel(
    const float* __restrict__ bfc, const float* __restrict__ resid,
    const float* __restrict__ ln_w, const float* __restrict__ ln_b,
    float* __restrict__ out)
{
    extern __shared__ u32 dyn[];
    u32*  As  = dyn;
    u32*  Bs  = dyn + FC_AS_W;
    float* red = (float*)(dyn + FC_AS_W + FC_BS_W);   // [128][8]

    const u32* Wt = g_wh + 3 * 32768;
    const int tid  = threadIdx.x;
    const int wid  = tid >> 5;
    const int lane = tid & 31;
    const int g    = lane >> 2;
    const int t    = lane & 3;
    const int lr   = lane & 15;
    const int lc   = (lane >> 4) * 4;
    const int wm   = wid >> 2;   // 0..3
    const int wn   = wid & 3;    // 0..3
    const size_t m0 = (size_t)blockIdx.x * 128;

    const u32 as_b = smem_u32(As);
    const u32 bs_b = smem_u32(Bs);

    #pragma unroll
    for (int st = 0; st < 2; st++) {
        {
            int r = tid >> 2, c4 = tid & 3;
            cp16(as_b + (u32)(st * 128 * SW + r * SW + c4 * 4) * 4,
                 &g_attnout[(m0 + r) * 128 + st * 16 + c4 * 4]);
        }
        #pragma unroll
        for (int j = 0; j < 2; j++) {
            int idx = tid + j * 512; int r = idx >> 2, c4 = idx & 3;
            cp16(bs_b + (u32)(st * 256 * SW + r * SW + c4 * 4) * 4,
                 &Wt[(size_t)r * 128 + st * 16 + c4 * 4]);
        }
        CP_COMMIT();
    }

    float acc[2][8][4];
    #pragma unroll
    for (int a = 0; a < 2; a++)
        #pragma unroll
        for (int b = 0; b < 8; b++)
            #pragma unroll
            for (int c = 0; c < 4; c++) acc[a][b][c] = 0.0f;

    #pragma unroll 1
    for (int i = 0; i < 8; i++) {
        const int s = i & 1;
        if (i < 7) { CP_WAIT(1); } else { CP_WAIT(0); }
        __syncthreads();

        const u32 a0 = as_b + (u32)s * 128 * SW * 4;
        const u32 b0 = bs_b + (u32)s * 256 * SW * 4;
        #pragma unroll
        for (int c = 0; c < 2; c++) {
            u32 ra[2][4];
            #pragma unroll
            for (int mt = 0; mt < 2; mt++)
                ldmx4(ra[mt], a0 + (u32)((wm * 32 + mt * 16 + lr) * SW + c * 8 + lc) * 4);
            #pragma unroll
            for (int qq = 0; qq < 4; qq++) {
                u32 rb[4];
                ldmx4(rb, b0 + (u32)((wn * 64 + qq * 16 + lr) * SW + c * 8 + lc) * 4);
                #pragma unroll
                for (int mt = 0; mt < 2; mt++) {
                    mma_f16(acc[mt][2 * qq],     ra[mt], rb[0], rb[2]);
                    mma_f16(acc[mt][2 * qq + 1], ra[mt], rb[1], rb[3]);
                }
            }
        }
        __syncthreads();
        if (i < 6) {
            {
                int r = tid >> 2, c4 = tid & 3;
                cp16(as_b + (u32)(s * 128 * SW + r * SW + c4 * 4) * 4,
                     &g_attnout[(m0 + r) * 128 + (i + 2) * 16 + c4 * 4]);
            }
            #pragma unroll
            for (int j = 0; j < 2; j++) {
                int idx = tid + j * 512; int r = idx >> 2, c4 = idx & 3;
                cp16(bs_b + (u32)(s * 256 * SW + r * SW + c4 * 4) * 4,
                     &Wt[(size_t)r * 128 + (i + 2) * 16 + c4 * 4]);
            }
            CP_COMMIT();
        }
    }

    #pragma unroll
    for (int mt = 0; mt < 2; mt++) {
        #pragma unroll
        for (int rs = 0; rs < 2; rs++) {
            int rloc = wm * 32 + mt * 16 + g + 8 * rs;
            float s = 0.0f, sq = 0.0f;
            #pragma unroll
            for (int nt = 0; nt < 8; nt++) {
                int col = wn * 64 + nt * 8 + 2 * t;
                float2 rr = *(const float2*)&resid[(m0 + rloc) * 256 + col];
                float v0 = acc[mt][nt][2 * rs]     + bfc[col]     + rr.x;
                float v1 = acc[mt][nt][2 * rs + 1] + bfc[col + 1] + rr.y;
                acc[mt][nt][2 * rs]     = v0;
                acc[mt][nt][2 * rs + 1] = v1;
                s  += v0 + v1;
                sq += v0 * v0 + v1 * v1;
            }
            s  += __shfl_xor_sync(0xffffffffu, s, 1);
            s  += __shfl_xor_sync(0xffffffffu, s, 2);
            sq += __shfl_xor_sync(0xffffffffu, sq, 1);
            sq += __shfl_xor_sync(0xffffffffu, sq, 2);
            if (t == 0) {
                red[rloc * 8 + wn]     = s;
                red[rloc * 8 + 4 + wn] = sq;
            }
        }
    }
    __syncthreads();

    #pragma unroll
    for (int mt = 0; mt < 2; mt++) {
        #pragma unroll
        for (int rs = 0; rs < 2; rs++) {
            int rloc = wm * 32 + mt * 16 + g + 8 * rs;
            float s  = red[rloc * 8 + 0] + red[rloc * 8 + 1] + red[rloc * 8 + 2] + red[rloc * 8 + 3];
            float sq = red[rloc * 8 + 4] + red[rloc * 8 + 5] + red[rloc * 8 + 6] + red[rloc * 8 + 7];
            float mu   = s * (1.0f / 256.0f);
            float var  = sq * (1.0f / 256.0f) - mu * mu;
            float rstd = rsqrtf(var + 1e-6f);
            #pragma unroll
            for (int nt = 0; nt < 8; nt++) {
                int col = wn * 64 + nt * 8 + 2 * t;
                float2 lw = *(const float2*)&ln_w[col];
                float2 lb = *(const float2*)&ln_b[col];
                float2 o;
                o.x = (acc[mt][nt][2 * rs]     - mu) * rstd * lw.x + lb.x;
                o.y = (acc[mt][nt][2 * rs + 1] - mu) * rstd * lw.y + lb.y;
                *(float2*)&out[(m0 + rloc) * 256 + col] = o;
            }
        }
    }
}

// ---------------------------------------------------------------------------
extern "C" void kernel_launch(void* const* d_in, const int* in_sizes, int n_in,
                              void* d_out, int out_size)
{
    const float* q    = (const float*)d_in[0];
    const float* k    = (const float*)d_in[1];
    const float* v    = (const float*)d_in[2];
    const float* Wq   = (const float*)d_in[3];
    const float* bq   = (const float*)d_in[4];
    const float* Wk   = (const float*)d_in[5];
    const float* bk   = (const float*)d_in[6];
    const float* Wv   = (const float*)d_in[7];
    const float* bv   = (const float*)d_in[8];
    const float* Wfc  = (const float*)d_in[9];
    const float* bfc  = (const float*)d_in[10];
    const float* ln_w = (const float*)d_in[11];
    const float* ln_b = (const float*)d_in[12];

    float* out  = (float*)d_out;
    float* attn = out + OUT_ELEMS;

    static bool attr_set = false;
    if (!attr_set) {
        cudaFuncSetAttribute(attn_kernel,  cudaFuncAttributeMaxDynamicSharedMemorySize, AT_SMEM_BYTES);
        cudaFuncSetAttribute(fc_ln_kernel, cudaFuncAttributeMaxDynamicSharedMemorySize, FC_SMEM_BYTES);
        attr_set = true;
    }

    wconv<<<128, 256>>>(Wq, Wk, Wv, Wfc);
    gemm_proj<<<dim3(2, 512, 3), 256>>>(q, k, v, bq, bk, bv);
    attn_kernel<<<NBLH, 256, AT_SMEM_BYTES>>>(attn);
    fc_ln_kernel<<<512, 512, FC_SMEM_BYTES>>>(bfc, q, ln_w, ln_b, out);
}

// round 9
// speedup vs baseline: 1.8154x; 1.0581x over previous
#include <cuda_runtime.h>
#include <cuda_fp16.h>
#include <math.h>
#include <stdint.h>

typedef uint32_t u32;

#define MROWS 65536
#define NBLH  4096
#define OUT_ELEMS ((size_t)MROWS * 256)

// Scratch: fp16 pairs packed in u32 words (pairs along the k/d dimension)
__device__ u32 g_qh[(size_t)NBLH * 128 * 16];   // [blq][h][w][dk/2]
__device__ u32 g_kh[(size_t)NBLH * 128 * 16];
__device__ u32 g_vh[(size_t)NBLH * 128 * 16];
__device__ u32 g_attnout[(size_t)MROWS * 128];  // [m][d/2]
__device__ u32 g_wh[4 * 32768];                 // Wq,Wk,Wv,Wfc as fp16 pairs [n][k/2]

// ---------------------------------------------------------------------------
// helpers
// ---------------------------------------------------------------------------
__device__ __forceinline__ u32 f2h2(float lo, float hi) {
    __half2 h = __floats2half2_rn(lo, hi);
    return *reinterpret_cast<u32*>(&h);
}
__device__ __forceinline__ void mma_f16(float* d, const u32* a, u32 b0, u32 b1) {
    asm volatile(
        "mma.sync.aligned.m16n8k16.row.col.f32.f16.f16.f32 "
        "{%0,%1,%2,%3}, {%4,%5,%6,%7}, {%8,%9}, {%0,%1,%2,%3};"
        : "+f"(d[0]), "+f"(d[1]), "+f"(d[2]), "+f"(d[3])
        : "r"(a[0]), "r"(a[1]), "r"(a[2]), "r"(a[3]), "r"(b0), "r"(b1));
}
__device__ __forceinline__ void ldmx4(u32* r, u32 addr) {
    asm volatile("ldmatrix.sync.aligned.m8n8.x4.shared.b16 {%0,%1,%2,%3}, [%4];"
        : "=r"(r[0]), "=r"(r[1]), "=r"(r[2]), "=r"(r[3]) : "r"(addr));
}
__device__ __forceinline__ void ldmx4t(u32* r, u32 addr) {
    asm volatile("ldmatrix.sync.aligned.m8n8.x4.trans.shared.b16 {%0,%1,%2,%3}, [%4];"
        : "=r"(r[0]), "=r"(r[1]), "=r"(r[2]), "=r"(r[3]) : "r"(addr));
}
__device__ __forceinline__ u32 smem_u32(const void* p) {
    u32 a;
    asm("{ .reg .u64 t; cvta.to.shared.u64 t, %1; cvt.u32.u64 %0, t; }" : "=r"(a) : "l"(p));
    return a;
}
__device__ __forceinline__ void cp16(u32 dst, const void* src) {
    asm volatile("cp.async.cg.shared.global [%0], [%1], 16;" :: "r"(dst), "l"(src));
}
#define CP_COMMIT() asm volatile("cp.async.commit_group;")
#define CP_WAIT(n)  asm volatile("cp.async.wait_group %0;" :: "n"(n))

// row stride in u32 words for all [row][k] smem tiles (16 data + 4 pad)
#define SW 20

// ---------------------------------------------------------------------------
// Weight pre-conversion to packed fp16
// ---------------------------------------------------------------------------
__global__ void wconv(const float* __restrict__ Wq, const float* __restrict__ Wk,
                      const float* __restrict__ Wv, const float* __restrict__ Wfc)
{
    int i = blockIdx.x * 256 + threadIdx.x;   // 0..32767
    g_wh[i]             = f2h2(Wq[2 * i],  Wq[2 * i + 1]);
    g_wh[32768 + i]     = f2h2(Wk[2 * i],  Wk[2 * i + 1]);
    g_wh[2 * 32768 + i] = f2h2(Wv[2 * i],  Wv[2 * i + 1]);
    g_wh[3 * 32768 + i] = f2h2(Wfc[2 * i], Wfc[2 * i + 1]);
}

// ---------------------------------------------------------------------------
// Kernel A: QKV projection, FULL-N CTAs (fc_ln shape): 512 threads, 16 warps
// (4x4), block tile 128x256, warp tile 32x64, BK=32, 2-stage pipeline.
// X read exactly ONCE (was twice). grid (512, 3): y selects q/k/v.
// A: fp32 LDG -> cvt -> STS (reg double-buffer). B: cp.async fp16.
// ---------------------------------------------------------------------------
#define PJ_AS_W (2 * 128 * SW)     // 5120 words
#define PJ_BS_W (2 * 256 * SW)     // 10240 words
#define PJ_SMEM_BYTES ((PJ_AS_W + PJ_BS_W) * 4)   // 61440

__global__ __launch_bounds__(512, 1) void gemm_proj(
    const float* __restrict__ q, const float* __restrict__ k, const float* __restrict__ v,
    const float* __restrict__ bq, const float* __restrict__ bk, const float* __restrict__ bv)
{
    extern __shared__ u32 dyn[];
    u32* As = dyn;                 // [2][128*SW]
    u32* Bs = dyn + PJ_AS_W;       // [2][256*SW]

    const int z = blockIdx.y;
    const float* X    = (z == 0) ? q : (z == 1) ? k : v;
    const u32*   Wt   = g_wh + (size_t)z * 32768;
    const float* bias = (z == 0) ? bq : (z == 1) ? bk : bv;
    u32*         outp = (z == 0) ? g_qh : (z == 1) ? g_kh : g_vh;
    const float scale = (z == 0) ? 0.17677669529663687f : 1.0f;

    const int tid  = threadIdx.x;
    const int wid  = tid >> 5;
    const int lane = tid & 31;
    const int g    = lane >> 2;
    const int t    = lane & 3;
    const int lr   = lane & 15;
    const int lc   = (lane >> 4) * 4;
    const int wm   = wid >> 2;     // 0..3
    const int wn   = wid & 3;      // 0..3
    const int m0   = blockIdx.x * 128;

    const u32 as_b = smem_u32(As);
    const u32 bs_b = smem_u32(Bs);

    const int arow = tid >> 2;     // 0..127 (4 threads per row)
    const int aq   = tid & 3;      // 8 floats each

    float4 fa[2];
#define LDG_A(cc)                                                              \
    do {                                                                       \
        size_t _o = (size_t)(m0 + arow) * 256 + (cc) * 32 + aq * 8;            \
        fa[0] = *(const float4*)&X[_o]; fa[1] = *(const float4*)&X[_o + 4];    \
    } while (0)
#define STS_A(st)                                                              \
    do {                                                                       \
        u32* _d = &As[(st) * 128 * SW + arow * SW + aq * 4];                   \
        _d[0] = f2h2(fa[0].x, fa[0].y); _d[1] = f2h2(fa[0].z, fa[0].w);        \
        _d[2] = f2h2(fa[1].x, fa[1].y); _d[3] = f2h2(fa[1].z, fa[1].w);        \
    } while (0)
#define CP_B(st, cc)                                                           \
    do {                                                                       \
        _Pragma("unroll")                                                      \
        for (int _j = 0; _j < 2; _j++) {                                       \
            int _idx = tid + _j * 512; int _r = _idx >> 2, _c4 = _idx & 3;     \
            cp16(bs_b + (u32)((st) * 256 * SW + _r * SW + _c4 * 4) * 4,        \
                 &Wt[(size_t)_r * 128 + (cc) * 16 + _c4 * 4]);                 \
        }                                                                      \
    } while (0)

    // prologue
    LDG_A(0);
    CP_B(0, 0); CP_COMMIT();
    STS_A(0);
    LDG_A(1);
    CP_B(1, 1); CP_COMMIT();

    float acc[2][8][4];
    #pragma unroll
    for (int a = 0; a < 2; a++)
        #pragma unroll
        for (int b = 0; b < 8; b++)
            #pragma unroll
            for (int c = 0; c < 4; c++) acc[a][b][c] = 0.0f;

    #pragma unroll 1
    for (int i = 0; i < 8; i++) {
        const int s = i & 1;
        if (i < 7) { CP_WAIT(1); } else { CP_WAIT(0); }
        __syncthreads();

        const u32 a0 = as_b + (u32)s * 128 * SW * 4;
        const u32 b0 = bs_b + (u32)s * 256 * SW * 4;
        #pragma unroll
        for (int c = 0; c < 2; c++) {
            u32 ra[2][4];
            #pragma unroll
            for (int mt = 0; mt < 2; mt++)
                ldmx4(ra[mt], a0 + (u32)((wm * 32 + mt * 16 + lr) * SW + c * 8 + lc) * 4);
            #pragma unroll
            for (int qq = 0; qq < 4; qq++) {
                u32 rb[4];
                ldmx4(rb, b0 + (u32)((wn * 64 + qq * 16 + lr) * SW + c * 8 + lc) * 4);
                #pragma unroll
                for (int mt = 0; mt < 2; mt++) {
                    mma_f16(acc[mt][2 * qq],     ra[mt], rb[0], rb[2]);
                    mma_f16(acc[mt][2 * qq + 1], ra[mt], rb[1], rb[3]);
                }
            }
        }

        if (i < 7) STS_A(s ^ 1);     // A for chunk i+1
        __syncthreads();
        if (i < 6) {
            LDG_A(i + 2);
            CP_B(s, i + 2);
            CP_COMMIT();
        }
    }

    // epilogue: bias, scale, pack fp16 pairs, scatter to [blq][h][w][dk/2]
    const int blq = blockIdx.x;
    #pragma unroll
    for (int mt = 0; mt < 2; mt++) {
        #pragma unroll
        for (int nt = 0; nt < 8; nt++) {
            int n  = wn * 64 + nt * 8 + 2 * t;
            int h  = n >> 5;
            int dw = (n & 31) >> 1;
            float b0v = bias[n], b1v = bias[n + 1];
            #pragma unroll
            for (int rs = 0; rs < 2; rs++) {
                int ww = wm * 32 + mt * 16 + g + 8 * rs;
                outp[(((size_t)blq * 8 + h) * 128 + ww) * 16 + dw] =
                    f2h2((acc[mt][nt][2 * rs]     + b0v) * scale,
                         (acc[mt][nt][2 * rs + 1] + b1v) * scale);
            }
        }
    }
}

// ---------------------------------------------------------------------------
// Kernel B: attention per (b,l,h) — round-5 version verbatim (best measured).
// ---------------------------------------------------------------------------
__global__ __launch_bounds__(256, 2) void attn_kernel(float* __restrict__ attn_out)
{
    __shared__ u32 Qs[128 * SW];
    __shared__ u32 Ks[128 * SW];
    __shared__ u32 Vs[128 * SW];

    const int blk  = blockIdx.x;
    const int tid  = threadIdx.x;
    const int wid  = tid >> 5;
    const int lane = tid & 31;
    const int g    = lane >> 2;
    const int t    = lane & 3;
    const int lr   = lane & 15;
    const int lc   = (lane >> 4) * 4;

    const u32 qs_b = smem_u32(Qs);
    const u32 ks_b = smem_u32(Ks);
    const u32 vs_b = smem_u32(Vs);

    const uint4* Qg = (const uint4*)(g_qh + (size_t)blk * 2048);
    const uint4* Kg = (const uint4*)(g_kh + (size_t)blk * 2048);
    const uint4* Vg = (const uint4*)(g_vh + (size_t)blk * 2048);

    #pragma unroll
    for (int j = 0; j < 2; j++) {
        int idx = tid + j * 256;
        int row = idx >> 2, q4 = idx & 3;
        *(uint4*)&Qs[row * SW + q4 * 4] = Qg[idx];
        *(uint4*)&Ks[row * SW + q4 * 4] = Kg[idx];
        *(uint4*)&Vs[row * SW + q4 * 4] = Vg[idx];
    }
    __syncthreads();

    float sacc[16][4];
    #pragma unroll
    for (int nt = 0; nt < 16; nt++)
        #pragma unroll
        for (int c = 0; c < 4; c++) sacc[nt][c] = 0.0f;

    const int rbase16 = wid * 16;
    const int rbase   = rbase16 + g;
    #pragma unroll
    for (int c = 0; c < 2; c++) {
        u32 ra[4];
        ldmx4(ra, qs_b + (u32)((rbase16 + lr) * SW + c * 8 + lc) * 4);
        #pragma unroll
        for (int qq = 0; qq < 8; qq++) {
            u32 rb[4];
            ldmx4(rb, ks_b + (u32)((qq * 16 + lr) * SW + c * 8 + lc) * 4);
            mma_f16(sacc[2 * qq],     ra, rb[0], rb[2]);
            mma_f16(sacc[2 * qq + 1], ra, rb[1], rb[3]);
        }
    }

    float inv[2];
    #pragma unroll
    for (int rs = 0; rs < 2; rs++) {
        float mx = -1e30f;
        #pragma unroll
        for (int nt = 0; nt < 16; nt++) {
            mx = fmaxf(mx, sacc[nt][2 * rs]);
            mx = fmaxf(mx, sacc[nt][2 * rs + 1]);
        }
        mx = fmaxf(mx, __shfl_xor_sync(0xffffffffu, mx, 1));
        mx = fmaxf(mx, __shfl_xor_sync(0xffffffffu, mx, 2));
        float s = 0.0f;
        #pragma unroll
        for (int nt = 0; nt < 16; nt++) {
            float e0 = __expf(sacc[nt][2 * rs] - mx);
            float e1 = __expf(sacc[nt][2 * rs + 1] - mx);
            sacc[nt][2 * rs] = e0; sacc[nt][2 * rs + 1] = e1;
            s += e0 + e1;
        }
        s += __shfl_xor_sync(0xffffffffu, s, 1);
        s += __shfl_xor_sync(0xffffffffu, s, 2);
        inv[rs] = 1.0f / s;
    }
    #pragma unroll
    for (int nt = 0; nt < 16; nt++) {
        sacc[nt][0] *= inv[0]; sacc[nt][1] *= inv[0];
        sacc[nt][2] *= inv[1]; sacc[nt][3] *= inv[1];
    }

    const size_t abase = (size_t)blk * 16384;
    #pragma unroll
    for (int nt = 0; nt < 16; nt++) {
        int col = nt * 8 + 2 * t;
        float2 p0; p0.x = sacc[nt][0]; p0.y = sacc[nt][1];
        float2 p1; p1.x = sacc[nt][2]; p1.y = sacc[nt][3];
        *(float2*)&attn_out[abase + (size_t)rbase * 128 + col]       = p0;
        *(float2*)&attn_out[abase + (size_t)(rbase + 8) * 128 + col] = p1;
    }

    float oacc[4][4];
    #pragma unroll
    for (int nt = 0; nt < 4; nt++)
        #pragma unroll
        for (int c = 0; c < 4; c++) oacc[nt][c] = 0.0f;

    const int vrow_off = ((lane >> 3) & 1) * 8 + (lane & 7);
    const int vcol_off = (lane >> 4) * 4;
    #pragma unroll
    for (int ks = 0; ks < 8; ks++) {
        u32 af[4];
        af[0] = f2h2(sacc[2 * ks][0],     sacc[2 * ks][1]);
        af[1] = f2h2(sacc[2 * ks][2],     sacc[2 * ks][3]);
        af[2] = f2h2(sacc[2 * ks + 1][0], sacc[2 * ks + 1][1]);
        af[3] = f2h2(sacc[2 * ks + 1][2], sacc[2 * ks + 1][3]);
        #pragma unroll
        for (int np = 0; np < 2; np++) {
            u32 rb[4];
            ldmx4t(rb, vs_b + (u32)((16 * ks + vrow_off) * SW + np * 8 + vcol_off) * 4);
            mma_f16(oacc[2 * np],     af, rb[0], rb[1]);
            mma_f16(oacc[2 * np + 1], af, rb[2], rb[3]);
        }
    }

    const int blq = blk >> 3;
    const int h   = blk & 7;
    #pragma unroll
    for (int nt = 0; nt < 4; nt++) {
        #pragma unroll
        for (int rs = 0; rs < 2; rs++) {
            int m = blq * 128 + rbase + 8 * rs;
            g_attnout[(size_t)m * 128 + h * 16 + nt * 4 + t] =
                f2h2(oacc[nt][2 * rs], oacc[nt][2 * rs + 1]);
        }
    }
}

// ---------------------------------------------------------------------------
// Kernel C: FC + residual + LayerNorm — round-5 version verbatim.
// ---------------------------------------------------------------------------
#define FC_AS_W (2 * 128 * SW)
#define FC_BS_W (2 * 256 * SW)
#define FC_SMEM_BYTES ((FC_AS_W + FC_BS_W + 1024) * 4)

__global__ __launch_bounds__(512, 1) void fc_ln_kernel(
    const float* __restrict__ bfc, const float* __restrict__ resid,
    const float* __restrict__ ln_w, const float* __restrict__ ln_b,
    float* __restrict__ out)
{
    extern __shared__ u32 dyn[];
    u32*  As  = dyn;
    u32*  Bs  = dyn + FC_AS_W;
    float* red = (float*)(dyn + FC_AS_W + FC_BS_W);   // [128][8]

    const u32* Wt = g_wh + 3 * 32768;
    const int tid  = threadIdx.x;
    const int wid  = tid >> 5;
    const int lane = tid & 31;
    const int g    = lane >> 2;
    const int t    = lane & 3;
    const int lr   = lane & 15;
    const int lc   = (lane >> 4) * 4;
    const int wm   = wid >> 2;   // 0..3
    const int wn   = wid & 3;    // 0..3
    const size_t m0 = (size_t)blockIdx.x * 128;

    const u32 as_b = smem_u32(As);
    const u32 bs_b = smem_u32(Bs);

    #pragma unroll
    for (int st = 0; st < 2; st++) {
        {
            int r = tid >> 2, c4 = tid & 3;
            cp16(as_b + (u32)(st * 128 * SW + r * SW + c4 * 4) * 4,
                 &g_attnout[(m0 + r) * 128 + st * 16 + c4 * 4]);
        }
        #pragma unroll
        for (int j = 0; j < 2; j++) {
            int idx = tid + j * 512; int r = idx >> 2, c4 = idx & 3;
            cp16(bs_b + (u32)(st * 256 * SW + r * SW + c4 * 4) * 4,
                 &Wt[(size_t)r * 128 + st * 16 + c4 * 4]);
        }
        CP_COMMIT();
    }

    float acc[2][8][4];
    #pragma unroll
    for (int a = 0; a < 2; a++)
        #pragma unroll
        for (int b = 0; b < 8; b++)
            #pragma unroll
            for (int c = 0; c < 4; c++) acc[a][b][c] = 0.0f;

    #pragma unroll 1
    for (int i = 0; i < 8; i++) {
        const int s = i & 1;
        if (i < 7) { CP_WAIT(1); } else { CP_WAIT(0); }
        __syncthreads();

        const u32 a0 = as_b + (u32)s * 128 * SW * 4;
        const u32 b0 = bs_b + (u32)s * 256 * SW * 4;
        #pragma unroll
        for (int c = 0; c < 2; c++) {
            u32 ra[2][4];
            #pragma unroll
            for (int mt = 0; mt < 2; mt++)
                ldmx4(ra[mt], a0 + (u32)((wm * 32 + mt * 16 + lr) * SW + c * 8 + lc) * 4);
            #pragma unroll
            for (int qq = 0; qq < 4; qq++) {
                u32 rb[4];
                ldmx4(rb, b0 + (u32)((wn * 64 + qq * 16 + lr) * SW + c * 8 + lc) * 4);
                #pragma unroll
                for (int mt = 0; mt < 2; mt++) {
                    mma_f16(acc[mt][2 * qq],     ra[mt], rb[0], rb[2]);
                    mma_f16(acc[mt][2 * qq + 1], ra[mt], rb[1], rb[3]);
                }
            }
        }
        __syncthreads();
        if (i < 6) {
            {
                int r = tid >> 2, c4 = tid & 3;
                cp16(as_b + (u32)(s * 128 * SW + r * SW + c4 * 4) * 4,
                     &g_attnout[(m0 + r) * 128 + (i + 2) * 16 + c4 * 4]);
            }
            #pragma unroll
            for (int j = 0; j < 2; j++) {
                int idx = tid + j * 512; int r = idx >> 2, c4 = idx & 3;
                cp16(bs_b + (u32)(s * 256 * SW + r * SW + c4 * 4) * 4,
                     &Wt[(size_t)r * 128 + (i + 2) * 16 + c4 * 4]);
            }
            CP_COMMIT();
        }
    }

    #pragma unroll
    for (int mt = 0; mt < 2; mt++) {
        #pragma unroll
        for (int rs = 0; rs < 2; rs++) {
            int rloc = wm * 32 + mt * 16 + g + 8 * rs;
            float s = 0.0f, sq = 0.0f;
            #pragma unroll
            for (int nt = 0; nt < 8; nt++) {
                int col = wn * 64 + nt * 8 + 2 * t;
                float2 rr = *(const float2*)&resid[(m0 + rloc) * 256 + col];
                float v0 = acc[mt][nt][2 * rs]     + bfc[col]     + rr.x;
                float v1 = acc[mt][nt][2 * rs + 1] + bfc[col + 1] + rr.y;
                acc[mt][nt][2 * rs]     = v0;
                acc[mt][nt][2 * rs + 1] = v1;
                s  += v0 + v1;
                sq += v0 * v0 + v1 * v1;
            }
            s  += __shfl_xor_sync(0xffffffffu, s, 1);
            s  += __shfl_xor_sync(0xffffffffu, s, 2);
            sq += __shfl_xor_sync(0xffffffffu, sq, 1);
            sq += __shfl_xor_sync(0xffffffffu, sq, 2);
            if (t == 0) {
                red[rloc * 8 + wn]     = s;
                red[rloc * 8 + 4 + wn] = sq;
            }
        }
    }
    __syncthreads();

    #pragma unroll
    for (int mt = 0; mt < 2; mt++) {
        #pragma unroll
        for (int rs = 0; rs < 2; rs++) {
            int rloc = wm * 32 + mt * 16 + g + 8 * rs;
            float s  = red[rloc * 8 + 0] + red[rloc * 8 + 1] + red[rloc * 8 + 2] + red[rloc * 8 + 3];
            float sq = red[rloc * 8 + 4] + red[rloc * 8 + 5] + red[rloc * 8 + 6] + red[rloc * 8 + 7];
            float mu   = s * (1.0f / 256.0f);
            float var  = sq * (1.0f / 256.0f) - mu * mu;
            float rstd = rsqrtf(var + 1e-6f);
            #pragma unroll
            for (int nt = 0; nt < 8; nt++) {
                int col = wn * 64 + nt * 8 + 2 * t;
                float2 lw = *(const float2*)&ln_w[col];
                float2 lb = *(const float2*)&ln_b[col];
                float2 o;
                o.x = (acc[mt][nt][2 * rs]     - mu) * rstd * lw.x + lb.x;
                o.y = (acc[mt][nt][2 * rs + 1] - mu) * rstd * lw.y + lb.y;
                *(float2*)&out[(m0 + rloc) * 256 + col] = o;
            }
        }
    }
}

// ---------------------------------------------------------------------------
extern "C" void kernel_launch(void* const* d_in, const int* in_sizes, int n_in,
                              void* d_out, int out_size)
{
    const float* q    = (const float*)d_in[0];
    const float* k    = (const float*)d_in[1];
    const float* v    = (const float*)d_in[2];
    const float* Wq   = (const float*)d_in[3];
    const float* bq   = (const float*)d_in[4];
    const float* Wk   = (const float*)d_in[5];
    const float* bk   = (const float*)d_in[6];
    const float* Wv   = (const float*)d_in[7];
    const float* bv   = (const float*)d_in[8];
    const float* Wfc  = (const float*)d_in[9];
    const float* bfc  = (const float*)d_in[10];
    const float* ln_w = (const float*)d_in[11];
    const float* ln_b = (const float*)d_in[12];

    float* out  = (float*)d_out;
    float* attn = out + OUT_ELEMS;

    static bool attr_set = false;
    if (!attr_set) {
        cudaFuncSetAttribute(gemm_proj,    cudaFuncAttributeMaxDynamicSharedMemorySize, PJ_SMEM_BYTES);
        cudaFuncSetAttribute(fc_ln_kernel, cudaFuncAttributeMaxDynamicSharedMemorySize, FC_SMEM_BYTES);
        attr_set = true;
    }

    wconv<<<128, 256>>>(Wq, Wk, Wv, Wfc);
    gemm_proj<<<dim3(512, 3), 512, PJ_SMEM_BYTES>>>(q, k, v, bq, bk, bv);
    attn_kernel<<<NBLH, 256>>>(attn);
    fc_ln_kernel<<<512, 512, FC_SMEM_BYTES>>>(bfc, q, ln_w, ln_b, out);
}